// round 14
// baseline (speedup 1.0000x reference)
#include <cuda_runtime.h>

#define BATCH 128
#define TSTEPS 1024
#define IDIM 256
#define HDIM 512
#define GDIM 2048
#define REC_CHUNK 128
#define HB (HDIM * BATCH)
typedef unsigned long long ull;

__device__ float g_xw[(size_t)TSTEPS * GDIM * BATCH];  // [t][g'][b]
__device__ float g_W2[128 * 512 * 4 * 8];              // [cta][j][kl][gate*(w,w)]
__device__ float g_Wih_t[IDIM * GDIM];                 // [i][g']
__device__ float g_bias[GDIM];
__device__ float g_hP[2 * HB];                         // [buf][j][b]
__device__ float g_c[BATCH * HDIM];
__device__ unsigned g_bar;

__device__ __forceinline__ void fma2(ull& d, ull a, ull b) {
    asm("fma.rn.f32x2 %0, %1, %2, %0;" : "+l"(d) : "l"(a), "l"(b));
}

// ------------------------------ init --------------------------------------
// g' = 16*cta + 4*kl + gate ; khid_global = 4*cta + kl
__global__ void init_kernel(const float* __restrict__ W_ih,
                            const float* __restrict__ W_hh,
                            const float* __restrict__ b_ih,
                            const float* __restrict__ b_hh) {
    int idx = blockIdx.x * blockDim.x + threadIdx.x;
    int stride = gridDim.x * blockDim.x;
    for (int p = idx; p < 128 * 512 * 16; p += stride) {
        int cta = p >> 13, r = p & 8191;
        int j = r >> 4, kl = (r >> 2) & 3, gate = r & 3;
        float v = W_hh[(size_t)(gate * 512 + cta * 4 + kl) * 512 + j];
        g_W2[(size_t)p * 2] = v;
        g_W2[(size_t)p * 2 + 1] = v;
    }
    for (int p = idx; p < IDIM * GDIM; p += stride) {
        int i = p >> 11, g = p & 2047;
        int gate = g & 3, kl = (g >> 2) & 3, khid = ((g >> 4) << 2) + kl;
        g_Wih_t[p] = W_ih[(size_t)(gate * 512 + khid) * 256 + i];
    }
    for (int p = idx; p < GDIM; p += stride) {
        int gate = p & 3, kl = (p >> 2) & 3, khid = ((p >> 4) << 2) + kl;
        g_bias[p] = b_ih[gate * 512 + khid] + b_hh[gate * 512 + khid];
    }
    if (idx == 0) g_bar = 0u;
}

// ----------------------------- xW GEMM ------------------------------------
#define GM_BK 32
#define AS_STRIDE 68
__global__ __launch_bounds__(256) void xw_gemm(const float* __restrict__ x) {
    __shared__ float As[GM_BK * AS_STRIDE];
    __shared__ float Bs[GM_BK * 128];
    const int by = blockIdx.y;
    const int t = by >> 1, b0 = (by & 1) * 64;
    const int n0 = blockIdx.x * 128;
    const int tid = threadIdx.x;
    const int tm = tid & 15, tn8 = (tid >> 4) * 8;
    const float* xbase = x + ((size_t)b0 * TSTEPS + t) * IDIM;

    float acc[4][8];
    #pragma unroll
    for (int m = 0; m < 4; m++)
        #pragma unroll
        for (int n = 0; n < 8; n++) acc[m][n] = 0.0f;

    for (int k0 = 0; k0 < IDIM; k0 += GM_BK) {
        #pragma unroll
        for (int l = 0; l < 2; l++) {
            int idx4 = tid + l * 256;
            int k4 = (idx4 & 7) * 4, row = idx4 >> 3;
            float4 v = *(const float4*)(xbase + (size_t)row * (TSTEPS * IDIM) + k0 + k4);
            As[(k4 + 0) * AS_STRIDE + row] = v.x;
            As[(k4 + 1) * AS_STRIDE + row] = v.y;
            As[(k4 + 2) * AS_STRIDE + row] = v.z;
            As[(k4 + 3) * AS_STRIDE + row] = v.w;
        }
        #pragma unroll
        for (int l = 0; l < 4; l++) {
            int idx4 = tid + l * 256;
            int n4 = (idx4 & 31) * 4, k = idx4 >> 5;
            *(float4*)(&Bs[k * 128 + n4]) =
                *(const float4*)(g_Wih_t + (size_t)(k0 + k) * GDIM + n0 + n4);
        }
        __syncthreads();
        #pragma unroll
        for (int k = 0; k < GM_BK; k++) {
            float4 a = *(const float4*)(&As[k * AS_STRIDE + tm * 4]);
            float4 p = *(const float4*)(&Bs[k * 128 + tn8]);
            float4 q = *(const float4*)(&Bs[k * 128 + tn8 + 4]);
            float av[4] = {a.x, a.y, a.z, a.w};
            float bv[8] = {p.x, p.y, p.z, p.w, q.x, q.y, q.z, q.w};
            #pragma unroll
            for (int m = 0; m < 4; m++)
                #pragma unroll
                for (int n = 0; n < 8; n++)
                    acc[m][n] = fmaf(av[m], bv[n], acc[m][n]);
        }
        __syncthreads();
    }
    #pragma unroll
    for (int n = 0; n < 8; n++) {
        float bz = g_bias[n0 + tn8 + n];
        float4 o = make_float4(acc[0][n] + bz, acc[1][n] + bz,
                               acc[2][n] + bz, acc[3][n] + bz);
        *(float4*)(g_xw + ((size_t)t * GDIM + n0 + tn8 + n) * BATCH + b0 + tm * 4) = o;
    }
}

// --------------------------- recurrent ------------------------------------
// Compute role: warp w = je slab (32 j), lane = bq (b-quad). Thread owns
//   4 khid x 4 gates x 4 b; per j: 1 LDG.128 (h, no dup) + 8 broadcast
//   LDS.128 (W dup) + 32 FFMA2. Partials -> P[je][g][kl][b].
// Reduce role: thread (khC = tid>>7, bC = tid&127): sum 16 je partials/gate,
//   activations, c in register, st.cg h.
__global__ __launch_bounds__(512, 1) void lstm_rec(int t0) {
    extern __shared__ float smem[];
    float* sW = smem;            // 16384 floats (64 KB): [j][kl][g*(w,w)]
    float* P  = smem + 16384;    // 32768 floats (128 KB): [je][g][kl][b]

    const int cta = blockIdx.x, tid = threadIdx.x;
    {
        const float* src = g_W2 + (size_t)cta * 16384;
        for (int p = tid; p < 16384; p += 512) sW[p] = src[p];
    }

    const int w  = tid >> 5;           // je slab 0..15
    const int bq = tid & 31;           // b quad 0..31
    const int jbase = w * 32;
    const float* wslab = sW + jbase * 32;
    float* Pw = P + w * 2048 + bq * 4; // + (g*4+kl)*128

    const int khC = tid >> 7, bC = tid & 127;
    const int cell = bC * HDIM + cta * 4 + khC;
    const float* Pr = P + khC * 128 + bC;   // + e*2048 + g*512
    const float* xwb = g_xw + (size_t)(cta * 16 + khC * 4) * BATCH + bC;
    float* hOut = g_hP + (size_t)(cta * 4 + khC) * BATCH + bC;

    float creg = (t0 == 0) ? 0.0f : g_c[cell];
    __syncthreads();

    float xv0, xv1, xv2, xv3;
    {
        const float* xp = xwb + (size_t)t0 * (GDIM * BATCH);
        xv0 = __ldg(xp); xv1 = __ldg(xp + BATCH);
        xv2 = __ldg(xp + 2 * BATCH); xv3 = __ldg(xp + 3 * BATCH);
    }

    for (int tl = 0; tl < REC_CHUNK; tl++) {
        const int t = t0 + tl;
        ull A0[16], A1[16];   // [kl*4+g], b-pair 0/1
        #pragma unroll
        for (int q = 0; q < 16; q++) { A0[q] = 0ull; A1[q] = 0ull; }

        if (t > 0) {
            const float* hb = g_hP + (size_t)(t & 1) * HB + bq * 4;
            ulonglong2 u[4];
            #pragma unroll
            for (int p = 0; p < 4; p++)
                u[p] = __ldcg((const ulonglong2*)(hb + (size_t)(jbase + p) * BATCH));
            #pragma unroll 4
            for (int jj = 0; jj < 32; jj++) {
                ulonglong2 cu = u[jj & 3];
                if (jj + 4 < 32)
                    u[jj & 3] = __ldcg((const ulonglong2*)(hb + (size_t)(jbase + jj + 4) * BATCH));
                const float* wj = wslab + jj * 32;
                #pragma unroll
                for (int kl = 0; kl < 4; kl++) {
                    ulonglong2 w01 = *(const ulonglong2*)(wj + kl * 8);
                    ulonglong2 w23 = *(const ulonglong2*)(wj + kl * 8 + 4);
                    fma2(A0[kl*4+0], cu.x, w01.x); fma2(A1[kl*4+0], cu.y, w01.x);
                    fma2(A0[kl*4+1], cu.x, w01.y); fma2(A1[kl*4+1], cu.y, w01.y);
                    fma2(A0[kl*4+2], cu.x, w23.x); fma2(A1[kl*4+2], cu.y, w23.x);
                    fma2(A0[kl*4+3], cu.x, w23.y); fma2(A1[kl*4+3], cu.y, w23.y);
                }
            }
        }

        #pragma unroll
        for (int kl = 0; kl < 4; kl++)
            #pragma unroll
            for (int g = 0; g < 4; g++) {
                ulonglong2 v; v.x = A0[kl*4+g]; v.y = A1[kl*4+g];
                *(ulonglong2*)(Pw + (g * 4 + kl) * 128) = v;
            }
        __syncthreads();

        float s0 = xv0, s1 = xv1, s2 = xv2, s3 = xv3;
        #pragma unroll
        for (int e = 0; e < 16; e++) {
            const float* pp = Pr + e * 2048;
            s0 += pp[0]; s1 += pp[512]; s2 += pp[1024]; s3 += pp[1536];
        }

        float ig = __fdividef(1.0f, 1.0f + __expf(-s0));
        float fg = __fdividef(1.0f, 1.0f + __expf(-s1));
        float gg = 1.0f - __fdividef(2.0f, __expf(2.0f * s2) + 1.0f);
        float og = __fdividef(1.0f, 1.0f + __expf(-s3));
        creg = fg * creg + ig * gg;
        float th = 1.0f - __fdividef(2.0f, __expf(2.0f * creg) + 1.0f);
        float hv = og * th;

        float* hp = hOut + (size_t)((t + 1) & 1) * HB;
        asm volatile("st.global.cg.f32 [%0], %1;" :: "l"(hp), "f"(hv) : "memory");

        if (tl + 1 < REC_CHUNK) {
            const float* xp = xwb + (size_t)(t + 1) * (GDIM * BATCH);
            xv0 = __ldg(xp); xv1 = __ldg(xp + BATCH);
            xv2 = __ldg(xp + 2 * BATCH); xv3 = __ldg(xp + 3 * BATCH);
        }

        unsigned bar_t = (unsigned)(t + 1) * 128u;
        __syncthreads();
        if (tid == 0) {
            asm volatile("red.release.gpu.global.add.u32 [%0], 1;" :: "l"(&g_bar) : "memory");
            unsigned v;
            do {
                asm volatile("ld.acquire.gpu.global.u32 %0, [%1];" : "=r"(v) : "l"(&g_bar) : "memory");
            } while (v < bar_t);
        }
        __syncthreads();
    }
    g_c[cell] = creg;
}

// ------------------------------- fc ----------------------------------------
__global__ void fc_kernel(const float* __restrict__ fc_w,
                          const float* __restrict__ fc_b,
                          float* __restrict__ out) {
    int b = blockIdx.x, tid = threadIdx.x;     // 128 x 128
    float s = 0.0f;
    for (int j = tid; j < HDIM; j += 128)
        s = fmaf(g_hP[(size_t)j * BATCH + b], fc_w[j], s);
    s += __shfl_down_sync(0xffffffffu, s, 16);
    s += __shfl_down_sync(0xffffffffu, s, 8);
    s += __shfl_down_sync(0xffffffffu, s, 4);
    s += __shfl_down_sync(0xffffffffu, s, 2);
    s += __shfl_down_sync(0xffffffffu, s, 1);
    __shared__ float red[4];
    if ((tid & 31) == 0) red[tid >> 5] = s;
    __syncthreads();
    if (tid == 0) out[b] = red[0] + red[1] + red[2] + red[3] + fc_b[0];
}

// ----------------------------- launcher ------------------------------------
extern "C" void kernel_launch(void* const* d_in, const int* in_sizes, int n_in,
                              void* d_out, int out_size) {
    const float* x    = (const float*)d_in[0];
    const float* W_ih = (const float*)d_in[1];
    const float* W_hh = (const float*)d_in[2];
    const float* b_ih = (const float*)d_in[3];
    const float* b_hh = (const float*)d_in[4];
    const float* fc_w = (const float*)d_in[5];
    const float* fc_b = (const float*)d_in[6];
    float* out = (float*)d_out;

    cudaFuncSetAttribute(lstm_rec, cudaFuncAttributeMaxDynamicSharedMemorySize, 196608);

    init_kernel<<<2048, 256>>>(W_ih, W_hh, b_ih, b_hh);
    dim3 gg(16, 2048);
    xw_gemm<<<gg, 256>>>(x);
    for (int c = 0; c < TSTEPS / REC_CHUNK; c++)
        lstm_rec<<<128, 512, 196608>>>(c * REC_CHUNK);
    fc_kernel<<<128, 128>>>(fc_w, fc_b, out);
}

// round 15
// speedup vs baseline: 1.0096x; 1.0096x over previous
#include <cuda_runtime.h>

#define BATCH 128
#define TSTEPS 1024
#define IDIM 256
#define HDIM 512
#define GDIM 2048
#define REC_CHUNK 128
#define HB (HDIM * BATCH)
typedef unsigned long long ull;

__device__ float g_xw[(size_t)TSTEPS * GDIM * BATCH];  // [t][g'][b]
__device__ float g_W2[128 * 512 * 4 * 8];              // [cta][j][kl][gate*(w,w)]
__device__ float g_Wih_t[IDIM * GDIM];                 // [i][g']
__device__ float g_bias[GDIM];
__device__ float g_hP[2 * HB];                         // [buf][j][b]
__device__ float g_c[BATCH * HDIM];
__device__ unsigned g_bar;

__device__ __forceinline__ ull pk2(float lo, float hi) {
    ull r; asm("mov.b64 %0, {%1, %2};" : "=l"(r) : "f"(lo), "f"(hi)); return r;
}
__device__ __forceinline__ void fma2(ull& d, ull a, ull b) {
    asm("fma.rn.f32x2 %0, %1, %2, %0;" : "+l"(d) : "l"(a), "l"(b));
}
__device__ __forceinline__ ull add2(ull a, ull b) {
    ull r; asm("add.rn.f32x2 %0, %1, %2;" : "=l"(r) : "l"(a), "l"(b)); return r;
}

// ------------------------------ init --------------------------------------
// g' = 16*cta + 4*kl + gate ; khid_global = 4*cta + kl
__global__ void init_kernel(const float* __restrict__ W_ih,
                            const float* __restrict__ W_hh,
                            const float* __restrict__ b_ih,
                            const float* __restrict__ b_hh) {
    int idx = blockIdx.x * blockDim.x + threadIdx.x;
    int stride = gridDim.x * blockDim.x;
    for (int p = idx; p < 128 * 512 * 16; p += stride) {
        int cta = p >> 13, r = p & 8191;
        int j = r >> 4, kl = (r >> 2) & 3, gate = r & 3;
        float v = W_hh[(size_t)(gate * 512 + cta * 4 + kl) * 512 + j];
        g_W2[(size_t)p * 2] = v;
        g_W2[(size_t)p * 2 + 1] = v;
    }
    for (int p = idx; p < IDIM * GDIM; p += stride) {
        int i = p >> 11, g = p & 2047;
        int gate = g & 3, kl = (g >> 2) & 3, khid = ((g >> 4) << 2) + kl;
        g_Wih_t[p] = W_ih[(size_t)(gate * 512 + khid) * 256 + i];
    }
    for (int p = idx; p < GDIM; p += stride) {
        int gate = p & 3, kl = (p >> 2) & 3, khid = ((p >> 4) << 2) + kl;
        g_bias[p] = b_ih[gate * 512 + khid] + b_hh[gate * 512 + khid];
    }
    if (idx == 0) g_bar = 0u;
}

// ----------------------------- xW GEMM (f32x2) -----------------------------
#define GM_BK 32
#define AS_STRIDE 68
__global__ __launch_bounds__(256) void xw_gemm(const float* __restrict__ x) {
    __shared__ float As[GM_BK * AS_STRIDE];
    __shared__ float Bs[GM_BK * 128];
    const int by = blockIdx.y;
    const int t = by >> 1, b0 = (by & 1) * 64;
    const int n0 = blockIdx.x * 128;
    const int tid = threadIdx.x;
    const int tm = tid & 15, tn8 = (tid >> 4) * 8;
    const float* xbase = x + ((size_t)b0 * TSTEPS + t) * IDIM;

    ull acc[2][8];   // m-pairs (b rows tm*4+0,1 / +2,3) x 8 n
    #pragma unroll
    for (int mp = 0; mp < 2; mp++)
        #pragma unroll
        for (int n = 0; n < 8; n++) acc[mp][n] = 0ull;

    for (int k0 = 0; k0 < IDIM; k0 += GM_BK) {
        #pragma unroll
        for (int l = 0; l < 2; l++) {
            int idx4 = tid + l * 256;
            int k4 = (idx4 & 7) * 4, row = idx4 >> 3;
            float4 v = *(const float4*)(xbase + (size_t)row * (TSTEPS * IDIM) + k0 + k4);
            As[(k4 + 0) * AS_STRIDE + row] = v.x;
            As[(k4 + 1) * AS_STRIDE + row] = v.y;
            As[(k4 + 2) * AS_STRIDE + row] = v.z;
            As[(k4 + 3) * AS_STRIDE + row] = v.w;
        }
        #pragma unroll
        for (int l = 0; l < 4; l++) {
            int idx4 = tid + l * 256;
            int n4 = (idx4 & 31) * 4, k = idx4 >> 5;
            *(float4*)(&Bs[k * 128 + n4]) =
                *(const float4*)(g_Wih_t + (size_t)(k0 + k) * GDIM + n0 + n4);
        }
        __syncthreads();
        #pragma unroll
        for (int k = 0; k < GM_BK; k++) {
            ulonglong2 ap = *(const ulonglong2*)(&As[k * AS_STRIDE + tm * 4]);
            float4 p = *(const float4*)(&Bs[k * 128 + tn8]);
            float4 q = *(const float4*)(&Bs[k * 128 + tn8 + 4]);
            float bv[8] = {p.x, p.y, p.z, p.w, q.x, q.y, q.z, q.w};
            #pragma unroll
            for (int n = 0; n < 8; n++) {
                ull s = pk2(bv[n], bv[n]);
                fma2(acc[0][n], ap.x, s);
                fma2(acc[1][n], ap.y, s);
            }
        }
        __syncthreads();
    }
    #pragma unroll
    for (int n = 0; n < 8; n++) {
        float bz = g_bias[n0 + tn8 + n];
        ull bz2 = pk2(bz, bz);
        ulonglong2 o;
        o.x = add2(acc[0][n], bz2);
        o.y = add2(acc[1][n], bz2);
        *(ulonglong2*)(g_xw + ((size_t)t * GDIM + n0 + tn8 + n) * BATCH + b0 + tm * 4) = o;
    }
}

// --------------------------- recurrent ------------------------------------
// Warp w = (je = w&7 : 64-j slab, khp = w>>3 : khid pair {2khp,2khp+1}).
// Lane bq = b-quad (32 lanes cover all 128 b -> no duplicated h loads).
// Thread: 2 khid x 4 gates x 4 b = 16 f32x2 accs. Per j: 1 LDG.128 (h) +
// 4 broadcast LDS.128 (W dup pairs) + 16 FFMA2.
// Reduce role: thread (khC = tid>>7, bC = tid&127): sum 8 je partials/gate.
__global__ __launch_bounds__(512, 1) void lstm_rec(int t0) {
    extern __shared__ float smem[];
    float* sW = smem;            // 16384 floats (64 KB): [j][kl][g*(w,w)]
    float* P  = smem + 16384;    // 16384 floats (64 KB): [je][g][kl][b]

    const int cta = blockIdx.x, tid = threadIdx.x;
    {
        const float* src = g_W2 + (size_t)cta * 16384;
        for (int p = tid; p < 16384; p += 512) sW[p] = src[p];
    }

    const int w  = tid >> 5;
    const int je = w & 7, khp = w >> 3;
    const int bq = tid & 31;
    const int jbase = je * 64;
    const float* wslab = sW + jbase * 32 + khp * 16;   // kl pair {2khp,2khp+1}
    float* Pw = P + je * 2048 + khp * 256 + bq * 4;    // + g*512 + i*128

    const int khC = tid >> 7, bC = tid & 127;
    const int cell = bC * HDIM + cta * 4 + khC;
    const float* Pr = P + khC * 128 + bC;              // + e*2048 + g*512
    const float* xwb = g_xw + (size_t)(cta * 16 + khC * 4) * BATCH + bC;
    float* hOut = g_hP + (size_t)(cta * 4 + khC) * BATCH + bC;

    float creg = (t0 == 0) ? 0.0f : g_c[cell];
    __syncthreads();

    float xv0, xv1, xv2, xv3;
    {
        const float* xp = xwb + (size_t)t0 * (GDIM * BATCH);
        xv0 = __ldg(xp); xv1 = __ldg(xp + BATCH);
        xv2 = __ldg(xp + 2 * BATCH); xv3 = __ldg(xp + 3 * BATCH);
    }

    for (int tl = 0; tl < REC_CHUNK; tl++) {
        const int t = t0 + tl;
        ull A[2][4][2];   // [khid i][gate][b-pair]
        #pragma unroll
        for (int i = 0; i < 2; i++)
            #pragma unroll
            for (int g = 0; g < 4; g++) { A[i][g][0] = 0ull; A[i][g][1] = 0ull; }

        if (t > 0) {
            const float* hb = g_hP + (size_t)(t & 1) * HB + (size_t)jbase * BATCH + bq * 4;
            ulonglong2 u[4];
            #pragma unroll
            for (int p = 0; p < 4; p++)
                u[p] = __ldcg((const ulonglong2*)(hb + (size_t)p * BATCH));
            #pragma unroll 4
            for (int jj = 0; jj < 64; jj++) {
                ulonglong2 cu = u[jj & 3];
                if (jj + 4 < 64)
                    u[jj & 3] = __ldcg((const ulonglong2*)(hb + (size_t)(jj + 4) * BATCH));
                const float* wj = wslab + jj * 32;
                #pragma unroll
                for (int i = 0; i < 2; i++) {
                    ulonglong2 w01 = *(const ulonglong2*)(wj + i * 8);
                    ulonglong2 w23 = *(const ulonglong2*)(wj + i * 8 + 4);
                    fma2(A[i][0][0], cu.x, w01.x); fma2(A[i][0][1], cu.y, w01.x);
                    fma2(A[i][1][0], cu.x, w01.y); fma2(A[i][1][1], cu.y, w01.y);
                    fma2(A[i][2][0], cu.x, w23.x); fma2(A[i][2][1], cu.y, w23.x);
                    fma2(A[i][3][0], cu.x, w23.y); fma2(A[i][3][1], cu.y, w23.y);
                }
            }
        }

        #pragma unroll
        for (int g = 0; g < 4; g++)
            #pragma unroll
            for (int i = 0; i < 2; i++) {
                ulonglong2 v; v.x = A[i][g][0]; v.y = A[i][g][1];
                *(ulonglong2*)(Pw + g * 512 + i * 128) = v;
            }
        __syncthreads();

        float s0 = xv0, s1 = xv1, s2 = xv2, s3 = xv3;
        #pragma unroll
        for (int e = 0; e < 8; e++) {
            const float* pp = Pr + e * 2048;
            s0 += pp[0]; s1 += pp[512]; s2 += pp[1024]; s3 += pp[1536];
        }

        float ig = __fdividef(1.0f, 1.0f + __expf(-s0));
        float fg = __fdividef(1.0f, 1.0f + __expf(-s1));
        float gg = 1.0f - __fdividef(2.0f, __expf(2.0f * s2) + 1.0f);
        float og = __fdividef(1.0f, 1.0f + __expf(-s3));
        creg = fg * creg + ig * gg;
        float th = 1.0f - __fdividef(2.0f, __expf(2.0f * creg) + 1.0f);
        float hv = og * th;

        float* hp = hOut + (size_t)((t + 1) & 1) * HB;
        asm volatile("st.global.cg.f32 [%0], %1;" :: "l"(hp), "f"(hv) : "memory");

        if (tl + 1 < REC_CHUNK) {
            const float* xp = xwb + (size_t)(t + 1) * (GDIM * BATCH);
            xv0 = __ldg(xp); xv1 = __ldg(xp + BATCH);
            xv2 = __ldg(xp + 2 * BATCH); xv3 = __ldg(xp + 3 * BATCH);
        }

        unsigned bar_t = (unsigned)(t + 1) * 128u;
        __syncthreads();
        if (tid == 0) {
            asm volatile("red.release.gpu.global.add.u32 [%0], 1;" :: "l"(&g_bar) : "memory");
            unsigned v;
            do {
                asm volatile("ld.acquire.gpu.global.u32 %0, [%1];" : "=r"(v) : "l"(&g_bar) : "memory");
            } while (v < bar_t);
        }
        __syncthreads();
    }
    g_c[cell] = creg;
}

// ------------------------------- fc ----------------------------------------
__global__ void fc_kernel(const float* __restrict__ fc_w,
                          const float* __restrict__ fc_b,
                          float* __restrict__ out) {
    int b = blockIdx.x, tid = threadIdx.x;     // 128 x 128
    float s = 0.0f;
    for (int j = tid; j < HDIM; j += 128)
        s = fmaf(g_hP[(size_t)j * BATCH + b], fc_w[j], s);
    s += __shfl_down_sync(0xffffffffu, s, 16);
    s += __shfl_down_sync(0xffffffffu, s, 8);
    s += __shfl_down_sync(0xffffffffu, s, 4);
    s += __shfl_down_sync(0xffffffffu, s, 2);
    s += __shfl_down_sync(0xffffffffu, s, 1);
    __shared__ float red[4];
    if ((tid & 31) == 0) red[tid >> 5] = s;
    __syncthreads();
    if (tid == 0) out[b] = red[0] + red[1] + red[2] + red[3] + fc_b[0];
}

// ----------------------------- launcher ------------------------------------
extern "C" void kernel_launch(void* const* d_in, const int* in_sizes, int n_in,
                              void* d_out, int out_size) {
    const float* x    = (const float*)d_in[0];
    const float* W_ih = (const float*)d_in[1];
    const float* W_hh = (const float*)d_in[2];
    const float* b_ih = (const float*)d_in[3];
    const float* b_hh = (const float*)d_in[4];
    const float* fc_w = (const float*)d_in[5];
    const float* fc_b = (const float*)d_in[6];
    float* out = (float*)d_out;

    cudaFuncSetAttribute(lstm_rec, cudaFuncAttributeMaxDynamicSharedMemorySize, 131072);

    init_kernel<<<2048, 256>>>(W_ih, W_hh, b_ih, b_hh);
    dim3 gg(16, 2048);
    xw_gemm<<<gg, 256>>>(x);
    for (int c = 0; c < TSTEPS / REC_CHUNK; c++)
        lstm_rec<<<128, 512, 131072>>>(c * REC_CHUNK);
    fc_kernel<<<128, 128>>>(fc_w, fc_b, out);
}